// round 14
// baseline (speedup 1.0000x reference)
#include <cuda_runtime.h>
#include <cuda_fp16.h>
#include <stdint.h>
#include <math.h>

// Problem constants
#define BB 8
#define SS 512
#define DD 1024
#define FF 4096
#define EE 8
#define HH 16
#define NTOK 4096              // B*S
#define NSLOT 8192             // NTOK * top2
#define MAXPAD 9216            // 8192 + 8*128 padding
#define MAXMT 72               // MAXPAD/128

// ---------------- scratch (device globals; no allocation) ----------------
__device__ __half g_hln  [NTOK * DD];
__device__ __half g_qkv  [NTOK * 3 * DD];
__device__ __half g_attn [NTOK * DD];
__device__ float  g_xres [NTOK * DD];
__device__ __half g_moein[NTOK * DD];    // fp16 (GEMM A)
__device__ __half g_h1  [MAXPAD * FF];
__device__ float  g_y   [MAXPAD * DD];

// fp16, transposed (K-major, [N][K]) weights
__device__ __half g_wt_qkv[3 * DD * DD];
__device__ __half g_wt_o  [DD * DD];
__device__ __half g_wt1   [EE * FF * DD];   // per e: [F][D]
__device__ __half g_wt2   [EE * DD * FF];   // per e: [D][F]

__device__ int   g_top_e[NSLOT];
__device__ float g_top_w[NSLOT];
__device__ int   g_counts[EE];
__device__ int   g_pad_off[EE + 1];
__device__ int   g_tile_expert[MAXMT];
__device__ int   g_n_mtiles;
__device__ int   g_tok_of_slot[MAXPAD];
__device__ int   g_slot_of[NSLOT];

// ---------------- helpers ----------------
__device__ __forceinline__ uint32_t smem_u32(const void* p) {
    uint32_t a;
    asm("{ .reg .u64 t; cvta.to.shared.u64 t, %1; cvt.u32.u64 %0, t; }" : "=r"(a) : "l"(p));
    return a;
}
__device__ __forceinline__ float gelu_tanh(float v) {
    const float c = 0.7978845608028654f;
    float u = c * (v + 0.044715f * v * v * v);
    return 0.5f * v * (1.0f + tanhf(u));
}

// ---------------- weight transpose + fp16 convert: src[R][C] -> dst[C][R] ----------------
// Tile: 64 src-rows x 32 src-cols; half2-coalesced writes (8 thr = 128B contiguous).
__global__ __launch_bounds__(256)
void transpose_round(const float* __restrict__ src, __half* __restrict__ dst, int R, int C) {
    __shared__ float t[32][65];
    const float* s = src + (size_t)blockIdx.z * R * C;
    __half*      d = dst + (size_t)blockIdx.z * R * C;
    int r0 = blockIdx.y * 64, c0 = blockIdx.x * 32;
    int tx = threadIdx.x & 31, ty = threadIdx.x >> 5;    // 32 x 8
    #pragma unroll
    for (int i = 0; i < 8; i++)
        t[tx][ty + 8 * i] = s[(size_t)(r0 + ty + 8 * i) * C + c0 + tx];
    __syncthreads();
    int dc = threadIdx.x >> 3;          // 0..31 dst row (= src col)
    int rb = (threadIdx.x & 7) * 8;     // 8 halves along r
    __half* drow = d + (size_t)(c0 + dc) * R + r0 + rb;
    #pragma unroll
    for (int j = 0; j < 4; j++) {
        __half2 h;
        h.x = __float2half_rn(t[dc][rb + 2 * j]);
        h.y = __float2half_rn(t[dc][rb + 2 * j + 1]);
        *(__half2*)(drow + 2 * j) = h;
    }
}

// ============ fp16 mma.sync GEMM: 128x256 CTA tile, 256 thr, warp 64x64 (2x4 grid) ============
// MODE 0: Ch = half(A*B)          MODE 1: Cf = A*B + aux(resid f32)
// MODE 2: Ch = half(gelu(Agather*B+b1))   MODE 3: Cf = A*B + b2
#define MM_STAGE_BYTES 49152   // 16KB A + 32KB B
#define MM_SMEM_BYTES  98304   // 2 stages

template<int MODE, int KDIM, int NDIM>
__global__ __launch_bounds__(256)
void gemm_mma(const __half* __restrict__ A, const __half* __restrict__ Wt,
              const float* __restrict__ aux, void* __restrict__ Cv) {
    int mt = blockIdx.y;
    if (MODE >= 2 && mt >= g_n_mtiles) return;
    const __half* Wb = Wt;
    const float* bias = aux;
    if (MODE >= 2) {
        int e = g_tile_expert[mt];
        Wb   = Wt + (size_t)e * KDIM * NDIM;
        bias = aux + (size_t)e * NDIM;
    }
    extern __shared__ __align__(16) char smem[];
    uint32_t sbase = smem_u32(smem);

    int tid = threadIdx.x;
    int lane = tid & 31, wid = tid >> 5;
    int bm = mt * 128, bn = blockIdx.x * 256;

    int rg = tid >> 3, cc = tid & 7;
    const __half* arow[4];
    #pragma unroll
    for (int i = 0; i < 4; i++) {
        int r = rg + i * 32;
        int m = (MODE == 2) ? g_tok_of_slot[bm + r] : (bm + r);
        arow[i] = A + (size_t)m * KDIM + cc * 8;
    }
    const __half* bbase = Wb + (size_t)(bn + rg) * KDIM + cc * 8;
    uint32_t sw = (uint32_t)(((cc ^ (rg & 7)) << 4) + rg * 128);

    int wr = wid & 1, wc = wid >> 1;
    int rowa_base = wr * 64 + (lane & 7) + ((lane >> 3) & 1) * 8;
    int lhiA = lane >> 4;
    uint32_t aswz = (uint32_t)((rowa_base & 7) << 4);
    int rowb2 = wc * 64 + (lane & 7) + ((lane >> 4) & 1) * 8;
    int lbB = (lane >> 3) & 1;
    uint32_t bswz = (uint32_t)((lane & 7) << 4);

    float acc[4][8][4];
    #pragma unroll
    for (int mi = 0; mi < 4; mi++)
        #pragma unroll
        for (int ni = 0; ni < 8; ni++)
            #pragma unroll
            for (int j = 0; j < 4; j++) acc[mi][ni][j] = 0.f;

    uint4 pa[4], pb[8];

    auto load_g = [&](int s) {
        int k0 = s * 64;
        #pragma unroll
        for (int i = 0; i < 4; i++) pa[i] = *(const uint4*)(arow[i] + k0);
        #pragma unroll
        for (int i = 0; i < 8; i++)
            pb[i] = *(const uint4*)(bbase + k0 + (size_t)i * 32 * KDIM);
    };
    auto store_s = [&](int buf) {
        char* ab = smem + buf * MM_STAGE_BYTES;
        char* bb = ab + 16384;
        #pragma unroll
        for (int i = 0; i < 4; i++)
            *(uint4*)(ab + sw + i * (32 * 128)) = pa[i];
        #pragma unroll
        for (int i = 0; i < 8; i++)
            *(uint4*)(bb + sw + i * (32 * 128)) = pb[i];
    };
    auto compute = [&](int buf) {
        uint32_t abase = sbase + buf * MM_STAGE_BYTES;
        uint32_t bbs   = abase + 16384;
        #pragma unroll
        for (int ks = 0; ks < 4; ks++) {
            uint32_t af[4][4];
            #pragma unroll
            for (int mi = 0; mi < 4; mi++) {
                uint32_t addr = abase + (uint32_t)((rowa_base + mi * 16) * 128)
                              + ((((uint32_t)(ks * 2 + lhiA)) << 4) ^ aswz);
                asm volatile("ldmatrix.sync.aligned.m8n8.x4.shared.b16 {%0,%1,%2,%3}, [%4];"
                    : "=r"(af[mi][0]), "=r"(af[mi][1]), "=r"(af[mi][2]), "=r"(af[mi][3])
                    : "r"(addr));
            }
            #pragma unroll
            for (int nj = 0; nj < 4; nj++) {
                uint32_t bf0, bf1, bf2, bf3;
                uint32_t addr = bbs + (uint32_t)((rowb2 + nj * 16) * 128)
                              + ((((uint32_t)(ks * 2 + lbB)) << 4) ^ bswz);
                asm volatile("ldmatrix.sync.aligned.m8n8.x4.shared.b16 {%0,%1,%2,%3}, [%4];"
                    : "=r"(bf0), "=r"(bf1), "=r"(bf2), "=r"(bf3) : "r"(addr));
                #pragma unroll
                for (int mi = 0; mi < 4; mi++) {
                    asm volatile("mma.sync.aligned.m16n8k16.row.col.f32.f16.f16.f32 "
                        "{%0,%1,%2,%3}, {%4,%5,%6,%7}, {%8,%9}, {%0,%1,%2,%3};"
                        : "+f"(acc[mi][2*nj][0]), "+f"(acc[mi][2*nj][1]),
                          "+f"(acc[mi][2*nj][2]), "+f"(acc[mi][2*nj][3])
                        : "r"(af[mi][0]), "r"(af[mi][1]), "r"(af[mi][2]), "r"(af[mi][3]),
                          "r"(bf0), "r"(bf1));
                    asm volatile("mma.sync.aligned.m16n8k16.row.col.f32.f16.f16.f32 "
                        "{%0,%1,%2,%3}, {%4,%5,%6,%7}, {%8,%9}, {%0,%1,%2,%3};"
                        : "+f"(acc[mi][2*nj+1][0]), "+f"(acc[mi][2*nj+1][1]),
                          "+f"(acc[mi][2*nj+1][2]), "+f"(acc[mi][2*nj+1][3])
                        : "r"(af[mi][0]), "r"(af[mi][1]), "r"(af[mi][2]), "r"(af[mi][3]),
                          "r"(bf2), "r"(bf3));
                }
            }
        }
    };

    const int NSTAGE = KDIM / 64;
    load_g(0);
    store_s(0);
    __syncthreads();
    for (int s = 0; s < NSTAGE; ++s) {
        int buf = s & 1;
        if (s + 1 < NSTAGE) load_g(s + 1);
        compute(buf);
        if (s + 1 < NSTAGE) store_s(buf ^ 1);
        __syncthreads();
    }

    int qr = lane >> 2, c2 = (lane & 3) * 2;
    __half* Ch = (__half*)Cv;
    float*  Cf = (float*)Cv;
    #pragma unroll
    for (int mi = 0; mi < 4; mi++) {
        int r0 = bm + wr * 64 + mi * 16 + qr;
        #pragma unroll
        for (int ni = 0; ni < 8; ni++) {
            int col = bn + wc * 64 + ni * 8 + c2;
            float v0 = acc[mi][ni][0], v1 = acc[mi][ni][1];
            float v2 = acc[mi][ni][2], v3 = acc[mi][ni][3];
            if (MODE == 1) {
                float2 ra = *(const float2*)(aux + (size_t)r0 * NDIM + col);
                float2 rb = *(const float2*)(aux + (size_t)(r0 + 8) * NDIM + col);
                v0 += ra.x; v1 += ra.y; v2 += rb.x; v3 += rb.y;
            }
            if (MODE >= 2) {
                float2 bz = *(const float2*)(bias + col);
                v0 += bz.x; v1 += bz.y; v2 += bz.x; v3 += bz.y;
                if (MODE == 2) {
                    v0 = gelu_tanh(v0); v1 = gelu_tanh(v1);
                    v2 = gelu_tanh(v2); v3 = gelu_tanh(v3);
                }
            }
            if (MODE == 0 || MODE == 2) {
                __half2 h0; h0.x = __float2half_rn(v0); h0.y = __float2half_rn(v1);
                __half2 h1; h1.x = __float2half_rn(v2); h1.y = __float2half_rn(v3);
                *(__half2*)(Ch + (size_t)r0 * NDIM + col)       = h0;
                *(__half2*)(Ch + (size_t)(r0 + 8) * NDIM + col) = h1;
            } else {
                *(float2*)(Cf + (size_t)r0 * NDIM + col)       = make_float2(v0, v1);
                *(float2*)(Cf + (size_t)(r0 + 8) * NDIM + col) = make_float2(v2, v3);
            }
        }
    }
}

// ---------------- LN1: fp16 out only ----------------
__global__ __launch_bounds__(256)
void ln_kernel(const float* __restrict__ x, const float* __restrict__ g,
               const float* __restrict__ b, __half* __restrict__ y) {
    int n = blockIdx.x;
    int tid = threadIdx.x;
    const float4* xr = (const float4*)(x + (size_t)n * DD);
    float4 v = xr[tid];
    float s  = v.x + v.y + v.z + v.w;
    float sq = v.x*v.x + v.y*v.y + v.z*v.z + v.w*v.w;
    __shared__ float red[2][8];
    int lane = tid & 31, wid = tid >> 5;
    #pragma unroll
    for (int o = 16; o > 0; o >>= 1) {
        s  += __shfl_down_sync(0xffffffffu, s,  o);
        sq += __shfl_down_sync(0xffffffffu, sq, o);
    }
    if (lane == 0) { red[0][wid] = s; red[1][wid] = sq; }
    __syncthreads();
    if (wid == 0) {
        float a = (lane < 8) ? red[0][lane] : 0.f;
        float c = (lane < 8) ? red[1][lane] : 0.f;
        #pragma unroll
        for (int o = 4; o > 0; o >>= 1) {
            a += __shfl_down_sync(0xffffffffu, a, o);
            c += __shfl_down_sync(0xffffffffu, c, o);
        }
        if (lane == 0) { red[0][0] = a; red[1][0] = c; }
    }
    __syncthreads();
    float mean = red[0][0] * (1.0f / DD);
    float var  = red[1][0] * (1.0f / DD) - mean * mean;
    float rstd = rsqrtf(var + 1e-5f);
    float4 gv = ((const float4*)g)[tid];
    float4 bv = ((const float4*)b)[tid];
    float4 o;
    o.x = (v.x - mean) * rstd * gv.x + bv.x;
    o.y = (v.y - mean) * rstd * gv.y + bv.y;
    o.z = (v.z - mean) * rstd * gv.z + bv.z;
    o.w = (v.w - mean) * rstd * gv.w + bv.w;
    __half2 h0; h0.x = __float2half_rn(o.x); h0.y = __float2half_rn(o.y);
    __half2 h1; h1.x = __float2half_rn(o.z); h1.y = __float2half_rn(o.w);
    __half2* yp = (__half2*)(y + (size_t)n * DD);
    yp[tid * 2]     = h0;
    yp[tid * 2 + 1] = h1;
}

// ---------------- LN2 + fused router (fp32 logits, top-2) ----------------
__global__ __launch_bounds__(256)
void ln2_gate_kernel(const float* __restrict__ x, const float* __restrict__ g,
                     const float* __restrict__ b, __half* __restrict__ y,
                     const float* __restrict__ w_gate) {
    int n = blockIdx.x;
    int tid = threadIdx.x;
    const float4* xr = (const float4*)(x + (size_t)n * DD);
    float4 v = xr[tid];
    float s  = v.x + v.y + v.z + v.w;
    float sq = v.x*v.x + v.y*v.y + v.z*v.z + v.w*v.w;
    __shared__ float red[2][8];
    __shared__ float gred[8][8];      // [warp][expert]
    int lane = tid & 31, wid = tid >> 5;
    #pragma unroll
    for (int o = 16; o > 0; o >>= 1) {
        s  += __shfl_down_sync(0xffffffffu, s,  o);
        sq += __shfl_down_sync(0xffffffffu, sq, o);
    }
    if (lane == 0) { red[0][wid] = s; red[1][wid] = sq; }
    __syncthreads();
    if (wid == 0) {
        float a = (lane < 8) ? red[0][lane] : 0.f;
        float c = (lane < 8) ? red[1][lane] : 0.f;
        #pragma unroll
        for (int o = 4; o > 0; o >>= 1) {
            a += __shfl_down_sync(0xffffffffu, a, o);
            c += __shfl_down_sync(0xffffffffu, c, o);
        }
        if (lane == 0) { red[0][0] = a; red[1][0] = c; }
    }
    __syncthreads();
    float mean = red[0][0] * (1.0f / DD);
    float var  = red[1][0] * (1.0f / DD) - mean * mean;
    float rstd = rsqrtf(var + 1e-5f);
    float4 gv = ((const float4*)g)[tid];
    float4 bv = ((const float4*)b)[tid];
    float o0 = (v.x - mean) * rstd * gv.x + bv.x;
    float o1 = (v.y - mean) * rstd * gv.y + bv.y;
    float o2 = (v.z - mean) * rstd * gv.z + bv.z;
    float o3 = (v.w - mean) * rstd * gv.w + bv.w;
    __half2 h0; h0.x = __float2half_rn(o0); h0.y = __float2half_rn(o1);
    __half2 h1; h1.x = __float2half_rn(o2); h1.y = __float2half_rn(o3);
    __half2* yp = (__half2*)(y + (size_t)n * DD);
    yp[tid * 2]     = h0;
    yp[tid * 2 + 1] = h1;

    // gate logits: this thread owns rows d = tid*4 .. tid*4+3 of w_gate [D][E]
    const float* wg = w_gate + (size_t)tid * 4 * EE;
    float la[EE];
    #pragma unroll
    for (int e = 0; e < EE; e++)
        la[e] = o0 * wg[e] + o1 * wg[EE + e] + o2 * wg[2*EE + e] + o3 * wg[3*EE + e];
    #pragma unroll
    for (int e = 0; e < EE; e++) {
        #pragma unroll
        for (int o = 16; o > 0; o >>= 1)
            la[e] += __shfl_down_sync(0xffffffffu, la[e], o);
    }
    if (lane == 0)
        #pragma unroll
        for (int e = 0; e < EE; e++) gred[wid][e] = la[e];
    __syncthreads();
    if (tid == 0) {
        float lg[EE];
        #pragma unroll
        for (int e = 0; e < EE; e++) {
            float a = 0.f;
            #pragma unroll
            for (int w = 0; w < 8; w++) a += gred[w][e];
            lg[e] = a;
        }
        int i0 = 0;
        #pragma unroll
        for (int e = 1; e < EE; e++) if (lg[e] > lg[i0]) i0 = e;
        int i1 = (i0 == 0) ? 1 : 0;
        #pragma unroll
        for (int e = 0; e < EE; e++)
            if (e != i0 && lg[e] > lg[i1]) i1 = e;
        float w0 = 1.f / (1.f + __expf(lg[i1] - lg[i0]));
        g_top_e[2*n]   = i0;  g_top_e[2*n+1]   = i1;
        g_top_w[2*n]   = w0;  g_top_w[2*n+1]   = 1.f - w0;
    }
}

// ---------------- causal flash attention (fp16 mma.sync, Q-tile 128) ----------------
// Block: (qt of 128, h, b), 256 threads (8 warps, each 16 q-rows).
// smem: Q@0 (16K), K@16K (8K), V^T@24K (8K), P@32K (8x2K). Total 48KB static.
__global__ __launch_bounds__(256)
void attn_mma_kernel(const __half* __restrict__ qkv, __half* __restrict__ o) {
    __shared__ __align__(16) char smem[49152];
    uint32_t sbase = smem_u32(smem);
    const int Qo = 0, Ko = 16384, Vo = 24576, Po = 32768;
    int qt = blockIdx.x, h = blockIdx.y, b = blockIdx.z;
    int tid = threadIdx.x, lane = tid & 31, wm = tid >> 5;

    // Q fill: 128 rows, 256 threads -> row = tid>>1, 4 chunks
    {
        int fr = tid >> 1, fc0 = (tid & 1) * 4;
        const __half* qr_ = qkv + (size_t)(b * SS + qt * 128 + fr) * (3 * DD) + h * 64;
        #pragma unroll
        for (int i = 0; i < 4; i++) {
            int cc = fc0 + i;
            uint4 v = *(const uint4*)(qr_ + cc * 8);
            *(uint4*)(smem + Qo + fr * 128 + ((cc ^ (fr & 7)) << 4)) = v;
        }
    }

    int qr = lane >> 2, lam = lane & 3;
    int rowa = (lane & 7) + ((lane >> 3) & 1) * 8;
    int lhiA = lane >> 4;
    uint32_t aswz = (uint32_t)((rowa & 7) << 4);
    int rowb2 = (lane & 7) + ((lane >> 4) & 1) * 8;
    int lbB = (lane >> 3) & 1;
    uint32_t bswz = (uint32_t)((lane & 7) << 4);

    float acc_o[8][4];
    #pragma unroll
    for (int ni = 0; ni < 8; ni++)
        #pragma unroll
        for (int j = 0; j < 4; j++) acc_o[ni][j] = 0.f;
    float m0 = -1e30f, m1 = -1e30f, l0 = 0.f, l1 = 0.f;

    int q0g = qt * 128 + wm * 16;     // this warp's first global q row
    int ktmax = 2 * qt + 1;

    for (int kt = 0; kt <= ktmax; ++kt) {
        // K fill: 64 rows, 256 threads -> row = tid>>2, 2 chunks
        {
            int fr = tid >> 2, fc0 = (tid & 3) * 2;
            const __half* kr_ = qkv + (size_t)(b * SS + kt * 64 + fr) * (3 * DD) + DD + h * 64;
            #pragma unroll
            for (int i = 0; i < 2; i++) {
                int cc = fc0 + i;
                uint4 v = *(const uint4*)(kr_ + cc * 8);
                *(uint4*)(smem + Ko + fr * 128 + ((cc ^ (fr & 7)) << 4)) = v;
            }
        }
        // V^T fill: key row = tid>>2, 16 d values
        {
            int fr = tid >> 2;
            int d0 = (tid & 3) * 16;
            const __half* vr_ = qkv + (size_t)(b * SS + kt * 64 + fr) * (3 * DD) + 2 * DD + h * 64;
            #pragma unroll
            for (int i = 0; i < 2; i++) {
                uint4 v = *(const uint4*)(vr_ + d0 + i * 8);
                const __half* hp = (const __half*)&v;
                #pragma unroll
                for (int j = 0; j < 8; j++) {
                    int dd = d0 + i * 8 + j;
                    *(__half*)(smem + Vo + dd * 128
                               + (((fr >> 3) ^ (dd & 7)) << 4) + (fr & 7) * 2) = hp[j];
                }
            }
        }
        __syncthreads();

        // ---- S = Q * K^T ----
        float accs[8][4];
        #pragma unroll
        for (int ni = 0; ni < 8; ni++)
            #pragma unroll
            for (int j = 0; j < 4; j++) accs[ni][j] = 0.f;
        #pragma unroll
        for (int ks = 0; ks < 4; ks++) {
            uint32_t a0, a1, a2, a3;
            uint32_t aad = sbase + Qo + (wm * 16 + rowa) * 128
                         + ((((uint32_t)(ks * 2 + lhiA)) << 4) ^ aswz);
            asm volatile("ldmatrix.sync.aligned.m8n8.x4.shared.b16 {%0,%1,%2,%3}, [%4];"
                : "=r"(a0), "=r"(a1), "=r"(a2), "=r"(a3) : "r"(aad));
            #pragma unroll
            for (int nj = 0; nj < 4; nj++) {
                uint32_t bf0, bf1, bf2, bf3;
                uint32_t bad = sbase + Ko + (rowb2 + nj * 16) * 128
                             + ((((uint32_t)(ks * 2 + lbB)) << 4) ^ bswz);
                asm volatile("ldmatrix.sync.aligned.m8n8.x4.shared.b16 {%0,%1,%2,%3}, [%4];"
                    : "=r"(bf0), "=r"(bf1), "=r"(bf2), "=r"(bf3) : "r"(bad));
                asm volatile("mma.sync.aligned.m16n8k16.row.col.f32.f16.f16.f32 "
                    "{%0,%1,%2,%3}, {%4,%5,%6,%7}, {%8,%9}, {%0,%1,%2,%3};"
                    : "+f"(accs[2*nj][0]), "+f"(accs[2*nj][1]),
                      "+f"(accs[2*nj][2]), "+f"(accs[2*nj][3])
                    : "r"(a0), "r"(a1), "r"(a2), "r"(a3), "r"(bf0), "r"(bf1));
                asm volatile("mma.sync.aligned.m16n8k16.row.col.f32.f16.f16.f32 "
                    "{%0,%1,%2,%3}, {%4,%5,%6,%7}, {%8,%9}, {%0,%1,%2,%3};"
                    : "+f"(accs[2*nj+1][0]), "+f"(accs[2*nj+1][1]),
                      "+f"(accs[2*nj+1][2]), "+f"(accs[2*nj+1][3])
                    : "r"(a0), "r"(a1), "r"(a2), "r"(a3), "r"(bf2), "r"(bf3));
            }
        }

        // ---- scale + causal mask + online softmax ----
        float tm0 = -1e30f, tm1 = -1e30f;
        #pragma unroll
        for (int ni = 0; ni < 8; ni++) {
            #pragma unroll
            for (int j = 0; j < 4; j++) {
                float s = accs[ni][j] * 0.125f;
                int key = kt * 64 + ni * 8 + 2 * lam + (j & 1);
                int qg  = q0g + qr + (j >> 1) * 8;
                if (key > qg) s = -1e30f;
                accs[ni][j] = s;
                if ((j >> 1) == 0) tm0 = fmaxf(tm0, s);
                else               tm1 = fmaxf(tm1, s);
            }
        }
        tm0 = fmaxf(tm0, __shfl_xor_sync(0xffffffffu, tm0, 1));
        tm0 = fmaxf(tm0, __shfl_xor_sync(0xffffffffu, tm0, 2));
        tm1 = fmaxf(tm1, __shfl_xor_sync(0xffffffffu, tm1, 1));
        tm1 = fmaxf(tm1, __shfl_xor_sync(0xffffffffu, tm1, 2));
        float mn0 = fmaxf(m0, tm0), mn1 = fmaxf(m1, tm1);
        float c0 = __expf(m0 - mn0), c1 = __expf(m1 - mn1);
        m0 = mn0; m1 = mn1;

        char* pw = smem + Po + wm * 2048;
        float ls0 = 0.f, ls1 = 0.f;
        #pragma unroll
        for (int ni = 0; ni < 8; ni++) {
            #pragma unroll
            for (int j = 0; j < 4; j++) {
                float mrow = (j >> 1) ? m1 : m0;
                __half ph = __float2half_rn(__expf(accs[ni][j] - mrow));
                float pr = __half2float(ph);
                if (j >> 1) ls1 += pr; else ls0 += pr;
                int col = ni * 8 + 2 * lam + (j & 1);
                int r   = qr + (j >> 1) * 8;
                *(__half*)(pw + r * 128 + (((col >> 3) ^ (r & 7)) << 4) + (col & 7) * 2) = ph;
            }
        }
        ls0 += __shfl_xor_sync(0xffffffffu, ls0, 1);
        ls0 += __shfl_xor_sync(0xffffffffu, ls0, 2);
        ls1 += __shfl_xor_sync(0xffffffffu, ls1, 1);
        ls1 += __shfl_xor_sync(0xffffffffu, ls1, 2);
        l0 = l0 * c0 + ls0;
        l1 = l1 * c1 + ls1;
        #pragma unroll
        for (int ni = 0; ni < 8; ni++) {
            acc_o[ni][0] *= c0; acc_o[ni][1] *= c0;
            acc_o[ni][2] *= c1; acc_o[ni][3] *= c1;
        }
        __syncwarp();

        // ---- O += P * V ----
        uint32_t pwb = sbase + Po + wm * 2048;
        #pragma unroll
        for (int ks = 0; ks < 4; ks++) {
            uint32_t a0, a1, a2, a3;
            uint32_t aad = pwb + rowa * 128
                         + ((((uint32_t)(ks * 2 + lhiA)) << 4) ^ aswz);
            asm volatile("ldmatrix.sync.aligned.m8n8.x4.shared.b16 {%0,%1,%2,%3}, [%4];"
                : "=r"(a0), "=r"(a1), "=r"(a2), "=r"(a3) : "r"(aad));
            #pragma unroll
            for (int nj = 0; nj < 4; nj++) {
                uint32_t bf0, bf1, bf2, bf3;
                uint32_t bad = sbase + Vo + (rowb2 + nj * 16) * 128
                             + ((((uint32_t)(ks * 2 + lbB)) << 4) ^ bswz);
                asm volatile("ldmatrix.sync.aligned.m8n8.x4.shared.b16 {%0,%1,%2,%3}, [%4];"
                    : "=r"(bf0), "=r"(bf1), "=r"(bf2), "=r"(bf3) : "r"(bad));
                asm volatile("mma.sync.aligned.m16n8k16.row.col.f32.f16.f16.f32 "
                    "{%0,%1,%2,%3}, {%4,%5,%6,%7}, {%8,%9}, {%0,%1,%2,%3};"
                    : "+f"(acc_o[2*nj][0]), "+f"(acc_o[2*nj][1]),
                      "+f"(acc_o[2*nj][2]), "+f"(acc_o[2*nj][3])
                    : "r"(a0), "r"(a1), "r"(a2), "r"(a3), "r"(bf0), "r"(bf1));
                asm volatile("mma.sync.aligned.m16n8k16.row.col.f32.f16.f16.f32 "
                    "{%0,%1,%2,%3}, {%4,%5,%6,%7}, {%8,%9}, {%0,%1,%2,%3};"
                    : "+f"(acc_o[2*nj+1][0]), "+f"(acc_o[2*nj+1][1]),
                      "+f"(acc_o[2*nj+1][2]), "+f"(acc_o[2*nj+1][3])
                    : "r"(a0), "r"(a1), "r"(a2), "r"(a3), "r"(bf2), "r"(bf3));
            }
        }
        __syncthreads();
    }

    // ---- epilogue ----
    float i0 = 1.f / l0, i1 = 1.f / l1;
    int r0 = b * SS + qt * 128 + wm * 16 + qr;
    #pragma unroll
    for (int ni = 0; ni < 8; ni++) {
        int col = h * 64 + ni * 8 + 2 * lam;
        __half2 w0; w0.x = __float2half_rn(acc_o[ni][0] * i0); w0.y = __float2half_rn(acc_o[ni][1] * i0);
        __half2 w1; w1.x = __float2half_rn(acc_o[ni][2] * i1); w1.y = __float2half_rn(acc_o[ni][3] * i1);
        *(__half2*)(o + (size_t)r0 * DD + col)       = w0;
        *(__half2*)(o + (size_t)(r0 + 8) * DD + col) = w1;
    }
}

// ---------------- routing ----------------
__global__ void counts_kernel() {
    __shared__ int cnt;
    if (threadIdx.x == 0) cnt = 0;
    __syncthreads();
    int e = blockIdx.x;
    int local = 0;
    for (int n = threadIdx.x; n < NTOK; n += 256)
        if (g_top_e[2*n] == e || g_top_e[2*n+1] == e) local++;
    atomicAdd(&cnt, local);
    __syncthreads();
    if (threadIdx.x == 0) g_counts[e] = cnt;
}

__global__ void offsets_kernel() {
    int off = 0;
    for (int e = 0; e < EE; ++e) {
        g_pad_off[e] = off;
        int seg = ((g_counts[e] + 127) >> 7) << 7;
        int t0 = off >> 7, t1 = (off + seg) >> 7;
        for (int t = t0; t < t1; ++t) g_tile_expert[t] = e;
        off += seg;
    }
    g_pad_off[EE] = off;
    g_n_mtiles = off >> 7;
}

__global__ __launch_bounds__(128)
void compact_kernel() {
    int e = blockIdx.x;
    int tid = threadIdx.x;
    int lane = tid & 31, wid = tid >> 5;
    __shared__ int warp_cnt[4];
    __shared__ int running;
    if (tid == 0) running = 0;
    __syncthreads();
    int base = g_pad_off[e];
    for (int c = 0; c < NTOK / 128; ++c) {
        int n = c * 128 + tid;
        int k = -1;
        if (g_top_e[2*n] == e) k = 0;
        else if (g_top_e[2*n+1] == e) k = 1;
        unsigned msk = __ballot_sync(0xffffffffu, k >= 0);
        int rank = __popc(msk & ((1u << lane) - 1));
        if (lane == 0) warp_cnt[wid] = __popc(msk);
        __syncthreads();
        int wbase = 0;
        #pragma unroll
        for (int w = 0; w < 4; ++w) if (w < wid) wbase += warp_cnt[w];
        int cur = running;
        if (k >= 0) {
            int slot = base + cur + wbase + rank;
            g_tok_of_slot[slot] = n;
            g_slot_of[2*n + k]  = slot;
        }
        __syncthreads();
        if (tid == 0)
            running = cur + warp_cnt[0] + warp_cnt[1] + warp_cnt[2] + warp_cnt[3];
        __syncthreads();
    }
    int cnt = running;
    int end = g_pad_off[e + 1];
    for (int s = base + cnt + tid; s < end; s += 128) g_tok_of_slot[s] = 0;
}

// ---------------- combine ----------------
__global__ __launch_bounds__(256)
void combine_kernel(const float* __restrict__ xres, const float* __restrict__ y,
                    float* __restrict__ out) {
    int n = blockIdx.x;
    int s0 = g_slot_of[2*n], s1 = g_slot_of[2*n+1];
    float wa = g_top_w[2*n], wb = g_top_w[2*n+1];
    int tid = threadIdx.x;
    float4 a  = ((const float4*)(xres + (size_t)n  * DD))[tid];
    float4 y0 = ((const float4*)(y + (size_t)s0 * DD))[tid];
    float4 y1 = ((const float4*)(y + (size_t)s1 * DD))[tid];
    float4 r;
    r.x = a.x + wa * y0.x + wb * y1.x;
    r.y = a.y + wa * y0.y + wb * y1.y;
    r.z = a.z + wa * y0.z + wb * y1.z;
    r.w = a.w + wa * y0.w + wb * y1.w;
    ((float4*)(out + (size_t)n * DD))[tid] = r;
}

// ---------------- launch ----------------
extern "C" void kernel_launch(void* const* d_in, const int* in_sizes, int n_in,
                              void* d_out, int out_size) {
    const float* x      = (const float*)d_in[0];
    const float* ln1_g  = (const float*)d_in[1];
    const float* ln1_b  = (const float*)d_in[2];
    const float* ln2_g  = (const float*)d_in[3];
    const float* ln2_b  = (const float*)d_in[4];
    const float* w_qkv  = (const float*)d_in[5];
    const float* w_o    = (const float*)d_in[6];
    const float* w_gate = (const float*)d_in[7];
    const float* w1     = (const float*)d_in[8];
    const float* b1     = (const float*)d_in[9];
    const float* w2     = (const float*)d_in[10];
    const float* b2     = (const float*)d_in[11];
    float* out = (float*)d_out;

    __half* p_hln;  cudaGetSymbolAddress((void**)&p_hln,  g_hln);
    __half* p_qkv;  cudaGetSymbolAddress((void**)&p_qkv,  g_qkv);
    __half* p_attn; cudaGetSymbolAddress((void**)&p_attn, g_attn);
    float*  p_xres; cudaGetSymbolAddress((void**)&p_xres, g_xres);
    __half* p_moein;cudaGetSymbolAddress((void**)&p_moein,g_moein);
    __half* p_h1;   cudaGetSymbolAddress((void**)&p_h1,   g_h1);
    float*  p_y;    cudaGetSymbolAddress((void**)&p_y,    g_y);
    __half* p_wqkv; cudaGetSymbolAddress((void**)&p_wqkv, g_wt_qkv);
    __half* p_wo;   cudaGetSymbolAddress((void**)&p_wo,   g_wt_o);
    __half* p_w1;   cudaGetSymbolAddress((void**)&p_w1,   g_wt1);
    __half* p_w2;   cudaGetSymbolAddress((void**)&p_w2,   g_wt2);

    cudaFuncSetAttribute(gemm_mma<0, DD, 3*DD>, cudaFuncAttributeMaxDynamicSharedMemorySize, MM_SMEM_BYTES);
    cudaFuncSetAttribute(gemm_mma<1, DD, DD>,   cudaFuncAttributeMaxDynamicSharedMemorySize, MM_SMEM_BYTES);
    cudaFuncSetAttribute(gemm_mma<2, DD, FF>,   cudaFuncAttributeMaxDynamicSharedMemorySize, MM_SMEM_BYTES);
    cudaFuncSetAttribute(gemm_mma<3, FF, DD>,   cudaFuncAttributeMaxDynamicSharedMemorySize, MM_SMEM_BYTES);

    // 0. weight transpose + fp16 convert (grid: C/32, R/64, Z)
    transpose_round<<<dim3(3*DD/32, DD/64, 1),  256>>>(w_qkv, p_wqkv, DD, 3*DD);
    transpose_round<<<dim3(DD/32,   DD/64, 1),  256>>>(w_o,   p_wo,   DD, DD);
    transpose_round<<<dim3(FF/32,   DD/64, EE), 256>>>(w1,    p_w1,   DD, FF);
    transpose_round<<<dim3(DD/32,   FF/64, EE), 256>>>(w2,    p_w2,   FF, DD);
    // 1. LN1
    ln_kernel<<<NTOK, 256>>>(x, ln1_g, ln1_b, p_hln);
    // 2. QKV GEMM (fp16 out)
    gemm_mma<0, DD, 3*DD><<<dim3(3*DD/256, NTOK/128), 256, MM_SMEM_BYTES>>>(p_hln, p_wqkv, nullptr, p_qkv);
    // 3. causal attention (fp16 tensor cores, Q-tile 128)
    attn_mma_kernel<<<dim3(SS/128, HH, BB), 256>>>(p_qkv, p_attn);
    // 4. O-proj + residual (fp32 out)
    gemm_mma<1, DD, DD><<<dim3(DD/256, NTOK/128), 256, MM_SMEM_BYTES>>>(p_attn, p_wo, x, p_xres);
    // 5. LN2 + fused router
    ln2_gate_kernel<<<NTOK, 256>>>(p_xres, ln2_g, ln2_b, p_moein, w_gate);
    // 6-8. routing
    counts_kernel<<<EE, 256>>>();
    offsets_kernel<<<1, 1>>>();
    compact_kernel<<<EE, 128>>>();
    // 9. MoE up: gelu(x @ w1[e] + b1[e]) (fp16 out)
    gemm_mma<2, DD, FF><<<dim3(FF/256, MAXMT), 256, MM_SMEM_BYTES>>>(p_moein, p_w1, b1, p_h1);
    // 10. MoE down: h1 @ w2[e] + b2[e] (fp32 out)
    gemm_mma<3, FF, DD><<<dim3(DD/256, MAXMT), 256, MM_SMEM_BYTES>>>(p_h1, p_w2, b2, p_y);
    // 11. combine + residual
    combine_kernel<<<NTOK, 256>>>(p_xres, p_y, out);
}